// round 12
// baseline (speedup 1.0000x reference)
#include <cuda_runtime.h>
#include <cstdint>

// ---------------- static config ----------------
#define PNX 256
#define PNS 128
#define PI_F 3.14159265358979323846f

#define SIGMA_MM   19.108280254777070f
#define INV_SIGMA  (1.0f/19.108280254777070f)
#define FILT_C2    900.91346f
#define FILT_SCALE (1.0f/1024.0f)
#define WIN_NSIG   3.5f
#define NREP       32
#define FFT_BLOCKS 128   // 2 warps (=2 lines) per block; 128 < 148 SMs -> co-resident

// ---------------- device scratch ----------------
__device__ float  g_img[NREP][PNX * PNX];   // zero-init at load; re-zeroed each call
__device__ float  g_imgsum[PNX * PNX];      // reduced image
__device__ float2 g_freqT[PNX * PNX];       // A->B, transposed [kx][row]
__device__ float2 g_freq[PNX * PNX];        // B->C, [y][kx-position]
__device__ unsigned g_bar_count = 0;
__device__ volatile unsigned g_bar_gen = 0;

// ---------------- packed f32x2 helpers (sm_100a) ----------------
__device__ __forceinline__ uint64_t pack2(float lo, float hi) {
    uint64_t r; asm("mov.b64 %0, {%1, %2};" : "=l"(r) : "f"(lo), "f"(hi)); return r;
}
__device__ __forceinline__ void unpack2(uint64_t v, float& lo, float& hi) {
    asm("mov.b64 {%0, %1}, %2;" : "=f"(lo), "=f"(hi) : "l"(v));
}
__device__ __forceinline__ uint64_t fma2(uint64_t a, uint64_t b, uint64_t c) {
    uint64_t r; asm("fma.rn.f32x2 %0, %1, %2, %3;" : "=l"(r) : "l"(a), "l"(b), "l"(c)); return r;
}
__device__ __forceinline__ uint64_t add2(uint64_t a, uint64_t b) {
    uint64_t r; asm("add.rn.f32x2 %0, %1, %2;" : "=l"(r) : "l"(a), "l"(b)); return r;
}

// ---------------- grid barrier ----------------
__device__ __forceinline__ void grid_barrier(unsigned nblocks) {
    __syncthreads();
    if (threadIdx.x == 0) {
        unsigned gen = g_bar_gen;
        __threadfence();
        if (atomicAdd(&g_bar_count, 1u) == nblocks - 1u) {
            g_bar_count = 0;
            __threadfence();
            g_bar_gen = gen + 1u;
        } else {
            while (g_bar_gen == gen) { }
            __threadfence();
        }
    }
    __syncthreads();
}

// ---------------- complex helpers ----------------
__device__ __forceinline__ float2 cadd(float2 a, float2 b){ return make_float2(a.x+b.x, a.y+b.y); }
__device__ __forceinline__ float2 csub(float2 a, float2 b){ return make_float2(a.x-b.x, a.y-b.y); }
__device__ __forceinline__ float2 cmul2(float2 a, float2 w){            // a*w
    return make_float2(a.x*w.x - a.y*w.y, a.x*w.y + a.y*w.x);
}
__device__ __forceinline__ float2 cmulc(float2 a, float2 w){            // a*conj(w)
    return make_float2(a.x*w.x + a.y*w.y, a.y*w.x - a.x*w.y);
}
__device__ __forceinline__ float2 shflx2(float2 v, int mask) {
    float2 r;
    r.x = __shfl_xor_sync(0xffffffffu, v.x, mask);
    r.y = __shfl_xor_sync(0xffffffffu, v.y, mask);
    return r;
}
__device__ __forceinline__ int brev8(int x) { return (int)(__brev((unsigned)x) >> 24); }

// ---------------- warp-level 256-pt FFT ----------------
// Layout: thread `lane` holds v[i] = element p = lane*8 + i.
// W[m] = cis(pi*m/128), m in [0,128).
// Forward: radix-2 DIF, natural input -> output holds X[brev8(p)] at position p.
// Inverse: radix-2 DIT, input holds X[brev8(p)] at position p -> natural output
// (unnormalized).
__device__ __forceinline__ void wfft_fwd(float2 v[8], int lane, const float2* __restrict__ W) {
    // cross-lane stages: span m = 128,64,32,16,8 (lane-bit 4..0)
#pragma unroll
    for (int s = 7; s >= 3; s--) {
        int lmask = 1 << (s - 3);
        int upper = (lane >> (s - 3)) & 1;
        int kbase = (lane & (lmask - 1)) * 8;     // lane part of (p mod m)
        int shift = 7 - s;                        // 128/m
#pragma unroll
        for (int i = 0; i < 8; i++) {
            float2 o = shflx2(v[i], lmask);
            float2 w = W[(kbase + i) << shift];
            if (upper) v[i] = cmulc(csub(o, v[i]), w);   // (u - v) * cis(-pi k/m)
            else       v[i] = cadd(v[i], o);             // u + v
        }
    }
    const float C = 0.70710678118654752f;
    // intra stage m=4: pairs (i, i+4), k=i, w=cis(-pi i/4)
#pragma unroll
    for (int i = 0; i < 4; i++) {
        float2 u = v[i], t = v[i + 4];
        float2 d = csub(u, t);
        v[i] = cadd(u, t);
        float2 w = (i == 0) ? make_float2(1.f, 0.f)
                 : (i == 1) ? make_float2(C, -C)
                 : (i == 2) ? make_float2(0.f, -1.f)
                            : make_float2(-C, -C);
        v[i + 4] = cmul2(d, w);
    }
    // intra stage m=2: pairs (b, b+2), k=b&1, w in {1, -i}
#pragma unroll
    for (int b = 0; b < 8; b += 4) {
#pragma unroll
        for (int q = 0; q < 2; q++) {
            int lo = b + q, hi = lo + 2;
            float2 u = v[lo], t = v[hi];
            float2 d = csub(u, t);
            v[lo] = cadd(u, t);
            v[hi] = q ? make_float2(d.y, -d.x) : d;      // d * (-i) if k=1
        }
    }
    // intra stage m=1: pairs (b, b+1), w=1
#pragma unroll
    for (int b = 0; b < 8; b += 2) {
        float2 u = v[b], t = v[b + 1];
        v[b]     = cadd(u, t);
        v[b + 1] = csub(u, t);
    }
}

__device__ __forceinline__ void wfft_inv(float2 v[8], int lane, const float2* __restrict__ W) {
    const float C = 0.70710678118654752f;
    // intra m=1
#pragma unroll
    for (int b = 0; b < 8; b += 2) {
        float2 u = v[b], t = v[b + 1];
        v[b]     = cadd(u, t);
        v[b + 1] = csub(u, t);
    }
    // intra m=2: w in {1, +i}
#pragma unroll
    for (int b = 0; b < 8; b += 4) {
#pragma unroll
        for (int q = 0; q < 2; q++) {
            int lo = b + q, hi = lo + 2;
            float2 u = v[lo], t = v[hi];
            float2 wv = q ? make_float2(-t.y, t.x) : t;  // t * (+i) if k=1
            v[lo] = cadd(u, wv);
            v[hi] = csub(u, wv);
        }
    }
    // intra m=4: w = cis(+pi i/4)
#pragma unroll
    for (int i = 0; i < 4; i++) {
        float2 u = v[i], t = v[i + 4];
        float2 w = (i == 0) ? make_float2(1.f, 0.f)
                 : (i == 1) ? make_float2(C, C)
                 : (i == 2) ? make_float2(0.f, 1.f)
                            : make_float2(-C, C);
        float2 wv = cmul2(t, w);
        v[i]     = cadd(u, wv);
        v[i + 4] = csub(u, wv);
    }
    // cross-lane stages: m = 8..128
#pragma unroll
    for (int s = 3; s <= 7; s++) {
        int lmask = 1 << (s - 3);
        int upper = (lane >> (s - 3)) & 1;
        int kbase = (lane & (lmask - 1)) * 8;
        int shift = 7 - s;
#pragma unroll
        for (int i = 0; i < 8; i++) {
            float2 o = shflx2(v[i], lmask);
            float2 w = W[(kbase + i) << shift];
            if (upper) v[i] = csub(o, cmul2(v[i], w));   // u - w*v
            else       v[i] = cadd(v[i], cmul2(o, w));   // u + w*v
        }
    }
}

__device__ __forceinline__ float freq_coord(int k) {
    return (k < 128) ? (k + 0.5f) * (1.0f / 128.0f)
                     : (k - 255.5f) * (1.0f / 128.0f);
}

// i0e(x) = exp(-x)*I0(x)
__device__ float i0e_dev(float x) {
    if (x > 8.0f) {
        float invx = 1.0f / x;
        float term = 1.0f, sum = 1.0f;
#pragma unroll
        for (int k = 1; k <= 6; k++) {
            float tk = (float)(2 * k - 1);
            term *= tk * tk * invx * (1.0f / (8.0f * (float)k));
            sum  += term;
        }
        return sum * rsqrtf(2.0f * PI_F * x);
    } else {
        float q = 0.25f * x * x;
        float term = 1.0f, sum = 1.0f;
#pragma unroll
        for (int k = 1; k <= 22; k++) {
            float ik = 1.0f / (float)k;
            term *= q * ik * ik;
            sum  += term;
        }
        return sum * __expf(-x);
    }
}

// ---------------- backprojection (unchanged — near REDG floor) ----------------
__global__ void k_bp(const float* __restrict__ proj, const float* __restrict__ tof,
                     const float* __restrict__ x1l, const float* __restrict__ y1l,
                     const float* __restrict__ x1r, const float* __restrict__ y1r,
                     const float* __restrict__ x2l, const float* __restrict__ y2l,
                     const float* __restrict__ x2r, const float* __restrict__ y2r,
                     int n) {
    int e = blockIdx.x * blockDim.x + threadIdx.x;
    if (e >= n) return;

    float x1 = 0.5f * (x1l[e] + x1r[e]);
    float y1 = 0.5f * (y1l[e] + y1r[e]);
    float x2 = 0.5f * (x2l[e] + x2r[e]);
    float y2 = 0.5f * (y2l[e] + y2r[e]);
    float ddx = x2 - x1, ddy = y2 - y1;
    float L = sqrtf(ddx * ddx + ddy * ddy);

    float step     = L * (1.0f / (float)PNS);
    float inv_step = (float)PNS / L;
    float center   = 0.5f * L + 0.15f * tof[e];

    float lo = (center - WIN_NSIG * SIGMA_MM) * inv_step - 0.5f;
    float hi = (center + WIN_NSIG * SIGMA_MM) * inv_step - 0.5f;
    int i0 = max(0,   (int)ceilf(lo));
    int i1 = min(127, (int)floorf(hi));
    if (i0 > i1) return;

    float dz = step * INV_SIGMA;
    float z0 = (((float)i0 + 0.5f) * step - center) * INV_SIGMA;
    float w  = proj[e] * step * __expf(-0.5f * z0 * z0);
    float r  = __expf(-dz * (z0 + 0.5f * dz));
    float c  = __expf(-dz * dz);

    float* img = g_img[e & (NREP - 1)];

    float t0f = ((float)i0 + 0.5f) * (1.0f / (float)PNS);
    uint64_t t2   = pack2(t0f, t0f);
    uint64_t dt2  = pack2(1.0f / (float)PNS, 1.0f / (float)PNS);
    uint64_t dd2  = pack2(ddx, ddy);
    uint64_t xy2  = pack2(x1, y1);
    uint64_t h2   = pack2(0.5f, 0.5f);
    uint64_t b2   = pack2(128.0f, 128.0f);

#pragma unroll 8
    for (int i = i0; i <= i1; i++) {
        uint64_t pxy = fma2(t2, dd2, xy2);
        uint64_t gxy = fma2(pxy, h2, b2);
        float gx, gy;
        unpack2(gxy, gx, gy);
        int ix = __float2int_rd(gx);
        int iy = __float2int_rd(gy);
        if ((unsigned)(ix | iy) < 256u)
            atomicAdd(&img[iy * PNX + ix], w);
        w *= r;  r *= c;
        t2 = add2(t2, dt2);
    }
}

// ---------------- replica reduction (full-chip, coalesced) ----------------
__global__ void k_reduce() {
    int p = blockIdx.x * blockDim.x + threadIdx.x;
    float acc = 0.0f;
#pragma unroll
    for (int rep = 0; rep < NREP; rep++) {
        acc += g_img[rep][p];
        g_img[rep][p] = 0.0f;
    }
    g_imgsum[p] = acc;
}

// ---------------- fused 2D FFT + filter (warp FFT, persistent) ----------------
// 128 blocks x 64 threads (2 warps); warp handles line = blockIdx*2 + wid.
__global__ void k_fft_all(float* __restrict__ out) {
    __shared__ float2 W[128];
    int wid  = threadIdx.x >> 5;
    int lane = threadIdx.x & 31;
    int line = blockIdx.x * 2 + wid;
    for (int m = threadIdx.x; m < 128; m += 64) {
        float s, c;
        sincospif((float)m * (1.0f / 128.0f), &s, &c);
        W[m] = make_float2(c, s);
    }
    __syncthreads();

    float2 v[8];

    // ---- Phase A: row forward FFT, store transposed (pos kx holds X[brev(kx)]) ----
    {
        int row = line;
        const float4* p4 = (const float4*)&g_imgsum[row * PNX + lane * 8];
        float4 a = p4[0], b = p4[1];
        v[0] = make_float2(a.x, 0.f); v[1] = make_float2(a.y, 0.f);
        v[2] = make_float2(a.z, 0.f); v[3] = make_float2(a.w, 0.f);
        v[4] = make_float2(b.x, 0.f); v[5] = make_float2(b.y, 0.f);
        v[6] = make_float2(b.z, 0.f); v[7] = make_float2(b.w, 0.f);
        wfft_fwd(v, lane, W);
#pragma unroll
        for (int i = 0; i < 8; i++)
            g_freqT[(lane * 8 + i) * PNX + row] = v[i];   // scattered store
    }

    grid_barrier(FFT_BLOCKS);

    // ---- Phase B: column FFT -> filter(brev coords) -> inverse column FFT ----
    {
        int c = line;                         // storage pos; true kx = brev8(c)
#pragma unroll
        for (int i = 0; i < 8; i++)
            v[i] = __ldcg(&g_freqT[c * PNX + lane * 8 + i]);   // coalesced
        wfft_fwd(v, lane, W);                 // pos q holds ky = brev8(q)

        float fx = freq_coord(brev8(c));
        float fx2 = fx * fx;
#pragma unroll
        for (int i = 0; i < 8; i++) {
            float fy = freq_coord(brev8(lane * 8 + i));
            float w0 = fmaf(fy, fy, fx2);
            float gn = FILT_SCALE / i0e_dev(w0 * FILT_C2);
            v[i].x *= gn;
            v[i].y *= gn;
        }
        wfft_inv(v, lane, W);                 // natural y out
#pragma unroll
        for (int i = 0; i < 8; i++)
            g_freq[(lane * 8 + i) * PNX + c] = v[i];      // scattered store
    }

    grid_barrier(FFT_BLOCKS);

    // ---- Phase C: row inverse FFT (input pos c holds kx=brev(c)) -> output ----
    {
        int row = line;
#pragma unroll
        for (int i = 0; i < 8; i++)
            v[i] = __ldcg(&g_freq[row * PNX + lane * 8 + i]); // coalesced
        wfft_inv(v, lane, W);
#pragma unroll
        for (int i = 0; i < 8; i++)
            out[row * PNX + lane * 8 + i] = v[i].x;
    }
}

// ---------------- launch ----------------
extern "C" void kernel_launch(void* const* d_in, const int* in_sizes, int n_in,
                              void* d_out, int out_size) {
    const float* proj = (const float*)d_in[0];
    const float* tof  = (const float*)d_in[1];
    const float* x1l  = (const float*)d_in[2];
    const float* y1l  = (const float*)d_in[3];
    const float* x1r  = (const float*)d_in[4];
    const float* y1r  = (const float*)d_in[5];
    const float* x2l  = (const float*)d_in[6];
    const float* y2l  = (const float*)d_in[7];
    const float* x2r  = (const float*)d_in[8];
    const float* y2r  = (const float*)d_in[9];
    int n = in_sizes[0];

    k_bp<<<(n + 255) / 256, 256>>>(proj, tof, x1l, y1l, x1r, y1r,
                                   x2l, y2l, x2r, y2r, n);
    k_reduce<<<(PNX * PNX) / 256, 256>>>();
    k_fft_all<<<FFT_BLOCKS, 64>>>((float*)d_out);
}